// round 3
// baseline (speedup 1.0000x reference)
#include <cuda_runtime.h>
#include <math.h>

#define HN 320
#define NPLANE (HN*HN)
#define NB 16
#define NTOT (NB*2*NPLANE)
#define LPC 8
#define FTH 256
#define LAM_TV 0.005f
#define LAM_W  0.005f
#define INV_S2 0.70710678118654752f

__device__ float g_Z[NTOT];
__device__ float g_X[NTOT];
__device__ float g_T1[NTOT];
__device__ float g_T2[NTOT];
__device__ float g_ykT[NTOT];        // D*mask*y, transposed [b][c][w][h]
__device__ float g_mT[NB*NPLANE];    // mask, transposed [b][w][h]
__device__ float2 g_tw[HN];

// ---------------- twiddles ----------------
__global__ void k_tw() {
    int k = threadIdx.x;
    if (k < HN) {
        double a = -2.0 * 3.14159265358979323846 * (double)k / (double)HN;
        g_tw[k] = make_float2((float)cos(a), (float)sin(a));
    }
}

// ---------------- prep: transposed mask & D*mask*y ----------------
__global__ void __launch_bounds__(256) k_prep(const float* __restrict__ y,
                                              const float* __restrict__ mask) {
    __shared__ float sm[32][33], s0[32][33], s1[32][33];
    int b = blockIdx.x / 100, t = blockIdx.x % 100;
    int h0 = (t / 10) * 32, w0 = (t % 10) * 32;
    for (int i = threadIdx.x; i < 1024; i += 256) {
        int r = i >> 5, c = i & 31;
        sm[r][c] = mask[b*NPLANE + (h0+r)*HN + w0+c];
        s0[r][c] = y[(b*2+0)*NPLANE + (h0+r)*HN + w0+c];
        s1[r][c] = y[(b*2+1)*NPLANE + (h0+r)*HN + w0+c];
    }
    __syncthreads();
    for (int i = threadIdx.x; i < 1024; i += 256) {
        int ww = i >> 5, hh = i & 31;
        float sg = (((h0+hh) + (w0+ww)) & 1) ? -1.f : 1.f;
        float m = sm[hh][ww];
        int o = (w0+ww)*HN + h0+hh;
        g_mT[b*NPLANE + o] = m;
        g_ykT[(b*2+0)*NPLANE + o] = sg * m * s0[hh][ww];
        g_ykT[(b*2+1)*NPLANE + o] = sg * m * s1[hh][ww];
    }
}

// ---------------- 320-pt Stockham FFT (5*4*4*4), d=+1 fwd, d=-1 inv ----------------
__device__ __forceinline__ void stage_r5(const float* ar, const float* ai,
                                         float* br, float* bi, int lane, float d) {
    const float c1 = 0.30901699437494742f, c2 = -0.80901699437494745f;
    const float s1 = 0.95105651629515353f, s2 = 0.58778525229247312f;
#pragma unroll
    for (int ii = 0; ii < 2; ii++) {
        int p = lane + 32*ii;
        float v0r = ar[p],       v0i = ai[p];
        float v1r = ar[p+64],    v1i = ai[p+64];
        float v2r = ar[p+128],   v2i = ai[p+128];
        float v3r = ar[p+192],   v3i = ai[p+192];
        float v4r = ar[p+256],   v4i = ai[p+256];
        float t1r = v1r+v4r, t1i = v1i+v4i;
        float t2r = v2r+v3r, t2i = v2i+v3i;
        float t3r = v1r-v4r, t3i = v1i-v4i;
        float t4r = v2r-v3r, t4i = v2i-v3i;
        int o = 5*p;
        br[o] = v0r+t1r+t2r; bi[o] = v0i+t1i+t2i;
        float a1r = v0r + c1*t1r + c2*t2r, a1i = v0i + c1*t1i + c2*t2i;
        float b1r = s1*t3r + s2*t4r,       b1i = s1*t3i + s2*t4i;
        float a2r = v0r + c2*t1r + c1*t2r, a2i = v0i + c2*t1i + c1*t2i;
        float b2r = s2*t3r - s1*t4r,       b2i = s2*t3i - s1*t4i;
        br[o+1] = a1r + d*b1i;  bi[o+1] = a1i - d*b1r;
        br[o+2] = a2r + d*b2i;  bi[o+2] = a2i - d*b2r;
        br[o+3] = a2r - d*b2i;  bi[o+3] = a2i + d*b2r;
        br[o+4] = a1r - d*b1i;  bi[o+4] = a1i + d*b1r;
    }
}

template<int LS>
__device__ __forceinline__ void stage_r4(const float* ar, const float* ai,
                                         float* br, float* bi, const float2* tw,
                                         int lane, float d) {
    const int MS = HN / (LS * 4);
#pragma unroll
    for (int ii = 0; ii < 3; ii++) {
        int i = lane + 32*ii;
        if (i < 80) {
            int q = i % LS, p = i / LS;
            int base = q + LS*p;
            float vr[4], vi[4];
#pragma unroll
            for (int r = 0; r < 4; r++) {
                float xr = ar[base + LS*MS*r];
                float xi = ai[base + LS*MS*r];
                float2 w = tw[q*r*MS];
                float wr = w.x, wi = d * w.y;
                vr[r] = xr*wr - xi*wi;
                vi[r] = xr*wi + xi*wr;
            }
            float t0r = vr[0]+vr[2], t0i = vi[0]+vi[2];
            float t1r = vr[0]-vr[2], t1i = vi[0]-vi[2];
            float t2r = vr[1]+vr[3], t2i = vi[1]+vi[3];
            float t3r = vr[1]-vr[3], t3i = vi[1]-vi[3];
            int o = q + LS*4*p;
            br[o]      = t0r+t2r;    bi[o]      = t0i+t2i;
            br[o+LS]   = t1r+d*t3i;  bi[o+LS]   = t1i-d*t3r;
            br[o+2*LS] = t0r-t2r;    bi[o+2*LS] = t0i-t2i;
            br[o+3*LS] = t1r-d*t3i;  bi[o+3*LS] = t1i+d*t3r;
        }
    }
}

__device__ __forceinline__ void fft_line(float* Ar, float* Ai, float* Br, float* Bi,
                                         const float2* tw, int lane, float d) {
    stage_r5(Ar, Ai, Br, Bi, lane, d);            __syncwarp();
    stage_r4<5 >(Br, Bi, Ar, Ai, tw, lane, d);    __syncwarp();
    stage_r4<20>(Ar, Ai, Br, Bi, tw, lane, d);    __syncwarp();
    stage_r4<80>(Br, Bi, Ar, Ai, tw, lane, d);    __syncwarp();
}

// ---------------- generic: FFT lines + transposed write ----------------
__global__ void __launch_bounds__(FTH) k_fft_gen(const float* __restrict__ src,
                                                 float* __restrict__ dstA,
                                                 float* __restrict__ dstB,
                                                 float d, int signIn, int signOut, float scale) {
    __shared__ float Ar[LPC][321], Ai[LPC][321], Br[LPC][321], Bi[LPC][321];
    __shared__ float2 tw[HN];
    int img = blockIdx.x / 40, r0 = (blockIdx.x % 40) * LPC;
    for (int k = threadIdx.x; k < HN; k += FTH) tw[k] = g_tw[k];
    const float* sre = src + (img*2+0)*NPLANE;
    const float* sim = src + (img*2+1)*NPLANE;
    for (int i = threadIdx.x; i < LPC*HN; i += FTH) {
        int s = i / HN, w = i - s*HN;
        float sg = (signIn && (((r0+s)+w)&1)) ? -1.f : 1.f;
        Ar[s][w] = sg * sre[(r0+s)*HN + w];
        Ai[s][w] = sg * sim[(r0+s)*HN + w];
    }
    __syncthreads();
    int line = threadIdx.x >> 5, lane = threadIdx.x & 31;
    fft_line(Ar[line], Ai[line], Br[line], Bi[line], tw, lane, d);
    __syncthreads();
    for (int i = threadIdx.x; i < LPC*HN; i += FTH) {
        int s = i & (LPC-1), k = i >> 3;
        float sg = (signOut && ((k + r0 + s)&1)) ? -scale : scale;
        float vr = Ar[s][k]*sg, vi = Ai[s][k]*sg;
        int o = k*HN + r0 + s;
        dstA[(img*2+0)*NPLANE + o] = vr;
        dstA[(img*2+1)*NPLANE + o] = vi;
        if (dstB) {
            dstB[(img*2+0)*NPLANE + o] = vr;
            dstB[(img*2+1)*NPLANE + o] = vi;
        }
    }
}

// ---------------- fwd col-FFT + mask pointwise + inv col-FFT ----------------
__global__ void __launch_bounds__(FTH) k_fft_mid(const float* __restrict__ src,
                                                 float* __restrict__ dst) {
    __shared__ float Ar[LPC][321], Ai[LPC][321], Br[LPC][321], Bi[LPC][321];
    __shared__ float2 tw[HN];
    int img = blockIdx.x / 40, r0 = (blockIdx.x % 40) * LPC;
    for (int k = threadIdx.x; k < HN; k += FTH) tw[k] = g_tw[k];
    const float* sre = src + (img*2+0)*NPLANE;
    const float* sim = src + (img*2+1)*NPLANE;
    for (int i = threadIdx.x; i < LPC*HN; i += FTH) {
        int s = i / HN, w = i - s*HN;
        Ar[s][w] = sre[(r0+s)*HN + w];
        Ai[s][w] = sim[(r0+s)*HN + w];
    }
    __syncthreads();
    int line = threadIdx.x >> 5, lane = threadIdx.x & 31;
    fft_line(Ar[line], Ai[line], Br[line], Bi[line], tw, lane, 1.f);
    // pointwise per warp on its own line: u = m*(F2(Dz)/320) - D*m*y
    {
        const float* mrow = g_mT  + img*NPLANE       + (r0+line)*HN;
        const float* ykr  = g_ykT + (img*2+0)*NPLANE + (r0+line)*HN;
        const float* yki  = g_ykT + (img*2+1)*NPLANE + (r0+line)*HN;
        for (int k = lane; k < HN; k += 32) {
            float m = mrow[k];
            Ar[line][k] = Ar[line][k]*m - ykr[k];
            Ai[line][k] = Ai[line][k]*m - yki[k];
        }
        __syncwarp();
    }
    fft_line(Ar[line], Ai[line], Br[line], Bi[line], tw, lane, -1.f);
    __syncthreads();
    for (int i = threadIdx.x; i < LPC*HN; i += FTH) {
        int s = i & (LPC-1), k = i >> 3;
        int o = k*HN + r0 + s;
        dst[(img*2+0)*NPLANE + o] = Ar[s][k];
        dst[(img*2+1)*NPLANE + o] = Ai[s][k];
    }
}

// ---------------- inv row-FFT + fused z_step = z - g ----------------
__global__ void __launch_bounds__(FTH) k_fft_last(const float* __restrict__ src,
                                                  const float* __restrict__ zin,
                                                  float* __restrict__ zs) {
    __shared__ float Ar[LPC][321], Ai[LPC][321], Br[LPC][321], Bi[LPC][321];
    __shared__ float2 tw[HN];
    int img = blockIdx.x / 40, r0 = (blockIdx.x % 40) * LPC;
    for (int k = threadIdx.x; k < HN; k += FTH) tw[k] = g_tw[k];
    const float* sre = src + (img*2+0)*NPLANE;
    const float* sim = src + (img*2+1)*NPLANE;
    for (int i = threadIdx.x; i < LPC*HN; i += FTH) {
        int s = i / HN, w = i - s*HN;
        Ar[s][w] = sre[(r0+s)*HN + w];
        Ai[s][w] = sim[(r0+s)*HN + w];
    }
    __syncthreads();
    int line = threadIdx.x >> 5, lane = threadIdx.x & 31;
    fft_line(Ar[line], Ai[line], Br[line], Bi[line], tw, lane, -1.f);
    __syncthreads();
    const float sc = 1.f/320.f;
    for (int i = threadIdx.x; i < LPC*HN; i += FTH) {
        int s = i / HN, w = i - s*HN;
        float sg = (((r0+s)+w)&1) ? -sc : sc;
        int oR = (img*2+0)*NPLANE + (r0+s)*HN + w;
        int oI = (img*2+1)*NPLANE + (r0+s)*HN + w;
        zs[oR] = zin[oR] - sg*Ar[s][w];
        zs[oI] = zin[oI] - sg*Ai[s][w];
    }
}

// ---------------- TV prox: 5 fused Chambolle iterations per tile ----------------
#define TS 32
#define HL 6
#define TP 44
#define TPS 45
__global__ void __launch_bounds__(256) k_tv(const float* __restrict__ xin,
                                            float* __restrict__ xout) {
    __shared__ float sx[TP*TPS], su[TP*TPS], spx[TP*TPS], spy[TP*TPS];
    int plane = blockIdx.x / 100;
    int t = blockIdx.x % 100;
    int gy0 = (t / 10) * TS - HL;
    int gx0 = (t % 10) * TS - HL;
    const float* X = xin + plane*NPLANE;
    for (int i = threadIdx.x; i < TP*TP; i += 256) {
        int r = i / TP, c = i - r*TP;
        int gy = gy0 + r, gx = gx0 + c;
        float v = 0.f;
        if (gy >= 0 && gy < HN && gx >= 0 && gx < HN) v = X[gy*HN + gx];
        sx[r*TPS+c] = v;
        spx[r*TPS+c] = 0.f;
        spy[r*TPS+c] = 0.f;
    }
    __syncthreads();
    for (int it = 0; it < 5; it++) {
        for (int i = threadIdx.x; i < TP*TP; i += 256) {
            int r = i / TP, c = i - r*TP;
            int gy = gy0 + r, gx = gx0 + c;
            float px_c = spx[r*TPS+c];
            float px_l = (c > 0) ? spx[r*TPS+c-1] : 0.f;
            float dx = (gx == 0) ? px_c : ((gx == HN-1) ? -px_l : px_c - px_l);
            float py_c = spy[r*TPS+c];
            float py_u = (r > 0) ? spy[(r-1)*TPS+c] : 0.f;
            float dy = (gy == 0) ? py_c : ((gy == HN-1) ? -py_u : py_c - py_u);
            su[r*TPS+c] = sx[r*TPS+c] - LAM_TV * (dx + dy);
        }
        __syncthreads();
        for (int i = threadIdx.x; i < TP*TP; i += 256) {
            int r = i / TP, c = i - r*TP;
            int gy = gy0 + r, gx = gx0 + c;
            float uc = su[r*TPS+c];
            float gxv = 0.f, gyv = 0.f;
            if (gx < HN-1 && c < TP-1) gxv = su[r*TPS+c+1] - uc;
            if (gy < HN-1 && r < TP-1) gyv = su[(r+1)*TPS+c] - uc;
            float pnx = spx[r*TPS+c] + 0.25f*gxv;
            float pny = spy[r*TPS+c] + 0.25f*gyv;
            float nrm = sqrtf(pnx*pnx + pny*pny + 1e-8f);
            float inv = (nrm > 1.f) ? 1.f/nrm : 1.f;
            if (gy < 0 || gy >= HN || gx < 0 || gx >= HN) { pnx = 0.f; pny = 0.f; inv = 1.f; }
            spx[r*TPS+c] = pnx*inv;
            spy[r*TPS+c] = pny*inv;
        }
        __syncthreads();
    }
    float* O = xout + plane*NPLANE;
    for (int i = threadIdx.x; i < TS*TS; i += 256) {
        int r = i / TS + HL, c = i - (r-HL)*TS + HL;
        int gy = gy0 + r, gx = gx0 + c;
        float px_c = spx[r*TPS+c];
        float px_l = spx[r*TPS+c-1];
        float dx = (gx == 0) ? px_c : ((gx == HN-1) ? -px_l : px_c - px_l);
        float py_c = spy[r*TPS+c];
        float py_u = spy[(r-1)*TPS+c];
        float dy = (gy == 0) ? py_c : ((gy == HN-1) ? -py_u : py_c - py_u);
        O[gy*HN + gx] = sx[r*TPS+c] - LAM_TV * (dx + dy);
    }
}

// ---------------- 3-level Haar + soft-threshold + FISTA, 8x8 per thread ----------------
template<int n>
__device__ __forceinline__ void haar_fwd(float a[8][8]) {
#pragma unroll
    for (int r = 0; r < n; r++) {
        float t[8];
#pragma unroll
        for (int j = 0; j < n/2; j++) {
            t[j]     = (a[r][2*j] + a[r][2*j+1]) * INV_S2;
            t[j+n/2] = (a[r][2*j] - a[r][2*j+1]) * INV_S2;
        }
#pragma unroll
        for (int j = 0; j < n; j++) a[r][j] = t[j];
    }
#pragma unroll
    for (int c = 0; c < n; c++) {
        float t[8];
#pragma unroll
        for (int j = 0; j < n/2; j++) {
            t[j]     = (a[2*j][c] + a[2*j+1][c]) * INV_S2;
            t[j+n/2] = (a[2*j][c] - a[2*j+1][c]) * INV_S2;
        }
#pragma unroll
        for (int j = 0; j < n; j++) a[j][c] = t[j];
    }
}

template<int n>
__device__ __forceinline__ void haar_inv(float a[8][8]) {
#pragma unroll
    for (int c = 0; c < n; c++) {
        float t[8];
#pragma unroll
        for (int j = 0; j < n/2; j++) {
            t[2*j]   = (a[j][c] + a[j+n/2][c]) * INV_S2;
            t[2*j+1] = (a[j][c] - a[j+n/2][c]) * INV_S2;
        }
#pragma unroll
        for (int j = 0; j < n; j++) a[j][c] = t[j];
    }
#pragma unroll
    for (int r = 0; r < n; r++) {
        float t[8];
#pragma unroll
        for (int j = 0; j < n/2; j++) {
            t[2*j]   = (a[r][j] + a[r][j+n/2]) * INV_S2;
            t[2*j+1] = (a[r][j] - a[r][j+n/2]) * INV_S2;
        }
#pragma unroll
        for (int j = 0; j < n; j++) a[r][j] = t[j];
    }
}

__device__ __forceinline__ float softt(float v) {
    float m = fabsf(v) - LAM_W;
    return (m > 0.f) ? copysignf(m, v) : 0.f;
}

__global__ void __launch_bounds__(256) k_wav(const float* __restrict__ xtv,
                                             const float* __restrict__ xold,
                                             float* __restrict__ xnew,
                                             float* __restrict__ znew,
                                             float coef) {
    int tid = blockIdx.x * 256 + threadIdx.x;
    if (tid >= 32*1600) return;
    int plane = tid / 1600, blk = tid - plane*1600;
    int by = (blk / 40) * 8, bx = (blk % 40) * 8;
    int base = plane*NPLANE + by*HN + bx;
    float a[8][8];
#pragma unroll
    for (int r = 0; r < 8; r++) {
        float4 v0 = *(const float4*)(xtv + base + r*HN);
        float4 v1 = *(const float4*)(xtv + base + r*HN + 4);
        a[r][0]=v0.x; a[r][1]=v0.y; a[r][2]=v0.z; a[r][3]=v0.w;
        a[r][4]=v1.x; a[r][5]=v1.y; a[r][6]=v1.z; a[r][7]=v1.w;
    }
    haar_fwd<8>(a);
#pragma unroll
    for (int r = 0; r < 8; r++)
#pragma unroll
        for (int c = 0; c < 8; c++)
            if (r >= 4 || c >= 4) a[r][c] = softt(a[r][c]);
    haar_fwd<4>(a);
#pragma unroll
    for (int r = 0; r < 4; r++)
#pragma unroll
        for (int c = 0; c < 4; c++)
            if (r >= 2 || c >= 2) a[r][c] = softt(a[r][c]);
    haar_fwd<2>(a);
    a[0][1] = softt(a[0][1]);
    a[1][0] = softt(a[1][0]);
    a[1][1] = softt(a[1][1]);
    haar_inv<2>(a);
    haar_inv<4>(a);
    haar_inv<8>(a);
#pragma unroll
    for (int r = 0; r < 8; r++) {
        float4 xo0 = *(const float4*)(xold + base + r*HN);
        float4 xo1 = *(const float4*)(xold + base + r*HN + 4);
        float xov[8] = {xo0.x,xo0.y,xo0.z,xo0.w,xo1.x,xo1.y,xo1.z,xo1.w};
        float4 xn0, xn1, zn0, zn1;
        float xn[8], zn[8];
#pragma unroll
        for (int c = 0; c < 8; c++) {
            float v = a[r][c];
            xn[c] = v;
            zn[c] = v + coef*(v - xov[c]);
        }
        xn0 = make_float4(xn[0],xn[1],xn[2],xn[3]);
        xn1 = make_float4(xn[4],xn[5],xn[6],xn[7]);
        zn0 = make_float4(zn[0],zn[1],zn[2],zn[3]);
        zn1 = make_float4(zn[4],zn[5],zn[6],zn[7]);
        *(float4*)(xnew + base + r*HN)     = xn0;
        *(float4*)(xnew + base + r*HN + 4) = xn1;
        *(float4*)(znew + base + r*HN)     = zn0;
        *(float4*)(znew + base + r*HN + 4) = zn1;
    }
}

// ---------------- host ----------------
extern "C" void kernel_launch(void* const* d_in, const int* in_sizes, int n_in,
                              void* d_out, int out_size) {
    (void)in_sizes; (void)n_in; (void)out_size;
    const float* y = (const float*)d_in[0];
    const float* mask = (const float*)d_in[1];
    float* out = (float*)d_out;

    float *Z, *X, *T1, *T2;
    cudaGetSymbolAddress((void**)&Z,  g_Z);
    cudaGetSymbolAddress((void**)&X,  g_X);
    cudaGetSymbolAddress((void**)&T1, g_T1);
    cudaGetSymbolAddress((void**)&T2, g_T2);

    // FISTA momentum coefficients (deterministic)
    float coefs[15];
    {
        double t = 1.0;
        for (int k = 0; k < 15; k++) {
            double tn = (1.0 + sqrt(1.0 + 4.0*t*t)) / 2.0;
            coefs[k] = (float)((t - 1.0) / tn);
            t = tn;
        }
    }

    k_tw<<<1, 320>>>();
    k_prep<<<1600, 256>>>(y, mask);
    // x0 = ifft2c(y): inverse rows (D on input), then inverse cols (D + 1/320 on output), dual write
    k_fft_gen<<<640, FTH>>>(y, T1, nullptr, -1.f, 1, 0, 1.0f);
    k_fft_gen<<<640, FTH>>>(T1, X, Z, -1.f, 0, 1, 1.f/320.f);

    for (int it = 0; it < 15; it++) {
        k_fft_gen<<<640, FTH>>>(Z, T1, nullptr, 1.f, 1, 0, 1.f/320.f);
        k_fft_mid<<<640, FTH>>>(T1, T2);
        k_fft_last<<<640, FTH>>>(T2, Z, T1);          // T1 = z_step
        k_tv<<<3200, 256>>>(T1, T2);                  // T2 = x_tv
        float* xnew = (it == 14) ? out : X;
        k_wav<<<200, 256>>>(T2, X, xnew, Z, coefs[it]);
    }
}

// round 4
// speedup vs baseline: 1.0327x; 1.0327x over previous
#include <cuda_runtime.h>
#include <math.h>

#define HN 320
#define NPLANE (HN*HN)
#define NB 16
#define NTOT (NB*2*NPLANE)
#define LPC 4
#define FTH 128
#define GRPS (HN/LPC)            // 80 line-groups per image
#define FGRID (NB*GRPS)          // 1280
#define LAM_TV 0.005f
#define LAM_W  0.005f
#define INV_S2 0.70710678118654752f

__device__ float  g_Z[NTOT];
__device__ float  g_X[NTOT];
__device__ float  g_T1[NTOT];            // planar z_step
__device__ float  g_T2[NTOT];            // planar x_tv
__device__ float2 g_T1c[NB*NPLANE];      // complex temp (transposed)
__device__ float2 g_T2c[NB*NPLANE];      // complex temp (planar)
__device__ float2 g_ykc[NB*NPLANE];      // D*mask*y, transposed, complex
__device__ float  g_mT[NB*NPLANE];       // mask, transposed
__device__ float2 g_tw[HN];

// ---------------- twiddles ----------------
__global__ void k_tw() {
    int k = threadIdx.x;
    if (k < HN) {
        double a = -2.0 * 3.14159265358979323846 * (double)k / (double)HN;
        g_tw[k] = make_float2((float)cos(a), (float)sin(a));
    }
}

// ---------------- prep: transposed mask & D*mask*y (complex) ----------------
__global__ void __launch_bounds__(256) k_prep(const float* __restrict__ y,
                                              const float* __restrict__ mask) {
    __shared__ float sm[32][33], s0[32][33], s1[32][33];
    int b = blockIdx.x / 100, t = blockIdx.x % 100;
    int h0 = (t / 10) * 32, w0 = (t % 10) * 32;
    for (int i = threadIdx.x; i < 1024; i += 256) {
        int r = i >> 5, c = i & 31;
        sm[r][c] = mask[b*NPLANE + (h0+r)*HN + w0+c];
        s0[r][c] = y[(b*2+0)*NPLANE + (h0+r)*HN + w0+c];
        s1[r][c] = y[(b*2+1)*NPLANE + (h0+r)*HN + w0+c];
    }
    __syncthreads();
    for (int i = threadIdx.x; i < 1024; i += 256) {
        int ww = i >> 5, hh = i & 31;
        float sg = (((h0+hh) + (w0+ww)) & 1) ? -1.f : 1.f;
        float m = sm[hh][ww];
        int o = (w0+ww)*HN + h0+hh;
        g_mT[b*NPLANE + o] = m;
        g_ykc[b*NPLANE + o] = make_float2(sg*m*s0[hh][ww], sg*m*s1[hh][ww]);
    }
}

// ---------------- 320-pt Stockham FFT (5*4*4*4), d=+1 fwd, d=-1 inv ----------------
__device__ __forceinline__ void stage_r5(const float* ar, const float* ai,
                                         float* br, float* bi, int lane, float d) {
    const float c1 = 0.30901699437494742f, c2 = -0.80901699437494745f;
    const float s1 = 0.95105651629515353f, s2 = 0.58778525229247312f;
#pragma unroll
    for (int ii = 0; ii < 2; ii++) {
        int p = lane + 32*ii;
        float v0r = ar[p],       v0i = ai[p];
        float v1r = ar[p+64],    v1i = ai[p+64];
        float v2r = ar[p+128],   v2i = ai[p+128];
        float v3r = ar[p+192],   v3i = ai[p+192];
        float v4r = ar[p+256],   v4i = ai[p+256];
        float t1r = v1r+v4r, t1i = v1i+v4i;
        float t2r = v2r+v3r, t2i = v2i+v3i;
        float t3r = v1r-v4r, t3i = v1i-v4i;
        float t4r = v2r-v3r, t4i = v2i-v3i;
        int o = 5*p;
        br[o] = v0r+t1r+t2r; bi[o] = v0i+t1i+t2i;
        float a1r = v0r + c1*t1r + c2*t2r, a1i = v0i + c1*t1i + c2*t2i;
        float b1r = s1*t3r + s2*t4r,       b1i = s1*t3i + s2*t4i;
        float a2r = v0r + c2*t1r + c1*t2r, a2i = v0i + c2*t1i + c1*t2i;
        float b2r = s2*t3r - s1*t4r,       b2i = s2*t3i - s1*t4i;
        br[o+1] = a1r + d*b1i;  bi[o+1] = a1i - d*b1r;
        br[o+2] = a2r + d*b2i;  bi[o+2] = a2i - d*b2r;
        br[o+3] = a2r - d*b2i;  bi[o+3] = a2i + d*b2r;
        br[o+4] = a1r - d*b1i;  bi[o+4] = a1i + d*b1r;
    }
}

template<int LS>
__device__ __forceinline__ void stage_r4(const float* ar, const float* ai,
                                         float* br, float* bi, const float2* tw,
                                         int lane, float d) {
    const int MS = HN / (LS * 4);
#pragma unroll
    for (int ii = 0; ii < 3; ii++) {
        int i = lane + 32*ii;
        if (i < 80) {
            int q = i % LS, p = i / LS;
            int base = q + LS*p;
            float vr[4], vi[4];
#pragma unroll
            for (int r = 0; r < 4; r++) {
                float xr = ar[base + LS*MS*r];
                float xi = ai[base + LS*MS*r];
                float2 w = tw[q*r*MS];
                float wr = w.x, wi = d * w.y;
                vr[r] = xr*wr - xi*wi;
                vi[r] = xr*wi + xi*wr;
            }
            float t0r = vr[0]+vr[2], t0i = vi[0]+vi[2];
            float t1r = vr[0]-vr[2], t1i = vi[0]-vi[2];
            float t2r = vr[1]+vr[3], t2i = vi[1]+vi[3];
            float t3r = vr[1]-vr[3], t3i = vi[1]-vi[3];
            int o = q + LS*4*p;
            br[o]      = t0r+t2r;    bi[o]      = t0i+t2i;
            br[o+LS]   = t1r+d*t3i;  bi[o+LS]   = t1i-d*t3r;
            br[o+2*LS] = t0r-t2r;    bi[o+2*LS] = t0i-t2i;
            br[o+3*LS] = t1r-d*t3i;  bi[o+3*LS] = t1i+d*t3r;
        }
    }
}

__device__ __forceinline__ void fft_line(float* Ar, float* Ai, float* Br, float* Bi,
                                         const float2* tw, int lane, float d) {
    stage_r5(Ar, Ai, Br, Bi, lane, d);            __syncwarp();
    stage_r4<5 >(Br, Bi, Ar, Ai, tw, lane, d);    __syncwarp();
    stage_r4<20>(Ar, Ai, Br, Bi, tw, lane, d);    __syncwarp();
    stage_r4<80>(Br, Bi, Ar, Ai, tw, lane, d);    __syncwarp();
}

// ---------------- planar -> complex transposed (sign+scale at load) ----------------
__global__ void __launch_bounds__(FTH) k_fft_p2c(const float* __restrict__ src,
                                                 float2* __restrict__ dst,
                                                 float d, float scale) {
    __shared__ float Ar[LPC][321], Ai[LPC][321], Br[LPC][321], Bi[LPC][321];
    __shared__ float2 tw[HN];
    int img = blockIdx.x / GRPS, r0 = (blockIdx.x % GRPS) * LPC;
    for (int k = threadIdx.x; k < HN; k += FTH) tw[k] = g_tw[k];
    const float* sre = src + (img*2+0)*NPLANE;
    const float* sim = src + (img*2+1)*NPLANE;
    for (int i = threadIdx.x; i < LPC*HN; i += FTH) {
        int s = i / HN, w = i - s*HN;
        float sg = (((r0+s)+w)&1) ? -scale : scale;
        Ar[s][w] = sg * sre[(r0+s)*HN + w];
        Ai[s][w] = sg * sim[(r0+s)*HN + w];
    }
    __syncthreads();
    int line = threadIdx.x >> 5, lane = threadIdx.x & 31;
    fft_line(Ar[line], Ai[line], Br[line], Bi[line], tw, lane, d);
    __syncthreads();
    float2* D = dst + img*NPLANE;
    for (int i = threadIdx.x; i < LPC*HN; i += FTH) {
        int s = i & (LPC-1), k = i >> 2;
        D[k*HN + r0 + s] = make_float2(Ar[s][k], Ai[s][k]);
    }
}

// ---------------- complex -> planar transposed, dual dst (init pass 2) ----------------
__global__ void __launch_bounds__(FTH) k_fft_c2p(const float2* __restrict__ src,
                                                 float* __restrict__ dstA,
                                                 float* __restrict__ dstB,
                                                 float d, float scale) {
    __shared__ float Ar[LPC][321], Ai[LPC][321], Br[LPC][321], Bi[LPC][321];
    __shared__ float2 tw[HN];
    int img = blockIdx.x / GRPS, r0 = (blockIdx.x % GRPS) * LPC;
    for (int k = threadIdx.x; k < HN; k += FTH) tw[k] = g_tw[k];
    const float2* S = src + img*NPLANE;
    for (int i = threadIdx.x; i < LPC*HN; i += FTH) {
        int s = i / HN, w = i - s*HN;
        float2 v = S[(r0+s)*HN + w];
        Ar[s][w] = v.x; Ai[s][w] = v.y;
    }
    __syncthreads();
    int line = threadIdx.x >> 5, lane = threadIdx.x & 31;
    fft_line(Ar[line], Ai[line], Br[line], Bi[line], tw, lane, d);
    __syncthreads();
    for (int i = threadIdx.x; i < LPC*HN; i += FTH) {
        int s = i & (LPC-1), k = i >> 2;
        float sg = ((k + r0 + s)&1) ? -scale : scale;
        float vr = Ar[s][k]*sg, vi = Ai[s][k]*sg;
        int o = k*HN + r0 + s;
        dstA[(img*2+0)*NPLANE + o] = vr;
        dstA[(img*2+1)*NPLANE + o] = vi;
        dstB[(img*2+0)*NPLANE + o] = vr;
        dstB[(img*2+1)*NPLANE + o] = vi;
    }
}

// ---------------- fwd col-FFT + mask pointwise + inv col-FFT (complex->complex) ----------------
__global__ void __launch_bounds__(FTH) k_fft_mid(const float2* __restrict__ src,
                                                 float2* __restrict__ dst) {
    __shared__ float Ar[LPC][321], Ai[LPC][321], Br[LPC][321], Bi[LPC][321];
    __shared__ float2 tw[HN];
    int img = blockIdx.x / GRPS, r0 = (blockIdx.x % GRPS) * LPC;
    for (int k = threadIdx.x; k < HN; k += FTH) tw[k] = g_tw[k];
    const float2* S = src + img*NPLANE;
    for (int i = threadIdx.x; i < LPC*HN; i += FTH) {
        int s = i / HN, w = i - s*HN;
        float2 v = S[(r0+s)*HN + w];
        Ar[s][w] = v.x; Ai[s][w] = v.y;
    }
    __syncthreads();
    int line = threadIdx.x >> 5, lane = threadIdx.x & 31;
    fft_line(Ar[line], Ai[line], Br[line], Bi[line], tw, lane, 1.f);
    {
        const float*  mrow = g_mT  + img*NPLANE + (r0+line)*HN;
        const float2* ykr  = g_ykc + img*NPLANE + (r0+line)*HN;
        for (int k = lane; k < HN; k += 32) {
            float m = mrow[k];
            float2 yk = ykr[k];
            Ar[line][k] = Ar[line][k]*m - yk.x;
            Ai[line][k] = Ai[line][k]*m - yk.y;
        }
        __syncwarp();
    }
    fft_line(Ar[line], Ai[line], Br[line], Bi[line], tw, lane, -1.f);
    __syncthreads();
    float2* D = dst + img*NPLANE;
    for (int i = threadIdx.x; i < LPC*HN; i += FTH) {
        int s = i & (LPC-1), k = i >> 2;
        D[k*HN + r0 + s] = make_float2(Ar[s][k], Ai[s][k]);
    }
}

// ---------------- inv row-FFT + fused z_step = z - g (complex->planar row-major) ----------------
__global__ void __launch_bounds__(FTH) k_fft_last(const float2* __restrict__ src,
                                                  const float* __restrict__ zin,
                                                  float* __restrict__ zs) {
    __shared__ float Ar[LPC][321], Ai[LPC][321], Br[LPC][321], Bi[LPC][321];
    __shared__ float2 tw[HN];
    int img = blockIdx.x / GRPS, r0 = (blockIdx.x % GRPS) * LPC;
    for (int k = threadIdx.x; k < HN; k += FTH) tw[k] = g_tw[k];
    const float2* S = src + img*NPLANE;
    for (int i = threadIdx.x; i < LPC*HN; i += FTH) {
        int s = i / HN, w = i - s*HN;
        float2 v = S[(r0+s)*HN + w];
        Ar[s][w] = v.x; Ai[s][w] = v.y;
    }
    __syncthreads();
    int line = threadIdx.x >> 5, lane = threadIdx.x & 31;
    fft_line(Ar[line], Ai[line], Br[line], Bi[line], tw, lane, -1.f);
    __syncthreads();
    const float sc = 1.f/320.f;
    for (int i = threadIdx.x; i < LPC*HN; i += FTH) {
        int s = i / HN, w = i - s*HN;
        float sg = (((r0+s)+w)&1) ? -sc : sc;
        int oR = (img*2+0)*NPLANE + (r0+s)*HN + w;
        int oI = (img*2+1)*NPLANE + (r0+s)*HN + w;
        zs[oR] = zin[oR] - sg*Ar[s][w];
        zs[oI] = zin[oI] - sg*Ai[s][w];
    }
}

// ---------------- TV prox: 5 fused Chambolle iterations per tile ----------------
#define TS 32
#define HL 6
#define TP 44
#define TPS 45
#define TVTH 512
__global__ void __launch_bounds__(TVTH) k_tv(const float* __restrict__ xin,
                                             float* __restrict__ xout) {
    __shared__ float sx[TP*TPS], su[TP*TPS], spx[TP*TPS], spy[TP*TPS];
    int plane = blockIdx.x / 100;
    int t = blockIdx.x % 100;
    int gy0 = (t / 10) * TS - HL;
    int gx0 = (t % 10) * TS - HL;
    const float* X = xin + plane*NPLANE;
    for (int i = threadIdx.x; i < TP*TP; i += TVTH) {
        int r = i / TP, c = i - r*TP;
        int gy = gy0 + r, gx = gx0 + c;
        float v = 0.f;
        if (gy >= 0 && gy < HN && gx >= 0 && gx < HN) v = X[gy*HN + gx];
        sx[r*TPS+c] = v;
        spx[r*TPS+c] = 0.f;
        spy[r*TPS+c] = 0.f;
    }
    __syncthreads();
    for (int it = 0; it < 5; it++) {
        for (int i = threadIdx.x; i < TP*TP; i += TVTH) {
            int r = i / TP, c = i - r*TP;
            int gy = gy0 + r, gx = gx0 + c;
            float px_c = spx[r*TPS+c];
            float px_l = (c > 0) ? spx[r*TPS+c-1] : 0.f;
            float dx = (gx == 0) ? px_c : ((gx == HN-1) ? -px_l : px_c - px_l);
            float py_c = spy[r*TPS+c];
            float py_u = (r > 0) ? spy[(r-1)*TPS+c] : 0.f;
            float dy = (gy == 0) ? py_c : ((gy == HN-1) ? -py_u : py_c - py_u);
            su[r*TPS+c] = sx[r*TPS+c] - LAM_TV * (dx + dy);
        }
        __syncthreads();
        for (int i = threadIdx.x; i < TP*TP; i += TVTH) {
            int r = i / TP, c = i - r*TP;
            int gy = gy0 + r, gx = gx0 + c;
            float uc = su[r*TPS+c];
            float gxv = 0.f, gyv = 0.f;
            if (gx < HN-1 && c < TP-1) gxv = su[r*TPS+c+1] - uc;
            if (gy < HN-1 && r < TP-1) gyv = su[(r+1)*TPS+c] - uc;
            float pnx = spx[r*TPS+c] + 0.25f*gxv;
            float pny = spy[r*TPS+c] + 0.25f*gyv;
            float nrm = sqrtf(pnx*pnx + pny*pny + 1e-8f);
            float inv = (nrm > 1.f) ? 1.f/nrm : 1.f;
            if (gy < 0 || gy >= HN || gx < 0 || gx >= HN) { pnx = 0.f; pny = 0.f; inv = 1.f; }
            spx[r*TPS+c] = pnx*inv;
            spy[r*TPS+c] = pny*inv;
        }
        __syncthreads();
    }
    float* O = xout + plane*NPLANE;
    for (int i = threadIdx.x; i < TS*TS; i += TVTH) {
        int r = i / TS + HL, c = i - (r-HL)*TS + HL;
        int gy = gy0 + r, gx = gx0 + c;
        float px_c = spx[r*TPS+c];
        float px_l = spx[r*TPS+c-1];
        float dx = (gx == 0) ? px_c : ((gx == HN-1) ? -px_l : px_c - px_l);
        float py_c = spy[r*TPS+c];
        float py_u = spy[(r-1)*TPS+c];
        float dy = (gy == 0) ? py_c : ((gy == HN-1) ? -py_u : py_c - py_u);
        O[gy*HN + gx] = sx[r*TPS+c] - LAM_TV * (dx + dy);
    }
}

// ---------------- 3-level Haar + soft-threshold + FISTA, 8x8 per thread ----------------
template<int n>
__device__ __forceinline__ void haar_fwd(float a[8][8]) {
#pragma unroll
    for (int r = 0; r < n; r++) {
        float t[8];
#pragma unroll
        for (int j = 0; j < n/2; j++) {
            t[j]     = (a[r][2*j] + a[r][2*j+1]) * INV_S2;
            t[j+n/2] = (a[r][2*j] - a[r][2*j+1]) * INV_S2;
        }
#pragma unroll
        for (int j = 0; j < n; j++) a[r][j] = t[j];
    }
#pragma unroll
    for (int c = 0; c < n; c++) {
        float t[8];
#pragma unroll
        for (int j = 0; j < n/2; j++) {
            t[j]     = (a[2*j][c] + a[2*j+1][c]) * INV_S2;
            t[j+n/2] = (a[2*j][c] - a[2*j+1][c]) * INV_S2;
        }
#pragma unroll
        for (int j = 0; j < n; j++) a[j][c] = t[j];
    }
}

template<int n>
__device__ __forceinline__ void haar_inv(float a[8][8]) {
#pragma unroll
    for (int c = 0; c < n; c++) {
        float t[8];
#pragma unroll
        for (int j = 0; j < n/2; j++) {
            t[2*j]   = (a[j][c] + a[j+n/2][c]) * INV_S2;
            t[2*j+1] = (a[j][c] - a[j+n/2][c]) * INV_S2;
        }
#pragma unroll
        for (int j = 0; j < n; j++) a[j][c] = t[j];
    }
#pragma unroll
    for (int r = 0; r < n; r++) {
        float t[8];
#pragma unroll
        for (int j = 0; j < n/2; j++) {
            t[2*j]   = (a[r][j] + a[r][j+n/2]) * INV_S2;
            t[2*j+1] = (a[r][j] - a[r][j+n/2]) * INV_S2;
        }
#pragma unroll
        for (int j = 0; j < n; j++) a[r][j] = t[j];
    }
}

__device__ __forceinline__ float softt(float v) {
    float m = fabsf(v) - LAM_W;
    return (m > 0.f) ? copysignf(m, v) : 0.f;
}

__global__ void __launch_bounds__(256) k_wav(const float* __restrict__ xtv,
                                             const float* __restrict__ xold,
                                             float* __restrict__ xnew,
                                             float* __restrict__ znew,
                                             float coef) {
    int tid = blockIdx.x * 256 + threadIdx.x;
    if (tid >= 32*1600) return;
    int plane = tid / 1600, blk = tid - plane*1600;
    int by = (blk / 40) * 8, bx = (blk % 40) * 8;
    int base = plane*NPLANE + by*HN + bx;
    float a[8][8];
#pragma unroll
    for (int r = 0; r < 8; r++) {
        float4 v0 = *(const float4*)(xtv + base + r*HN);
        float4 v1 = *(const float4*)(xtv + base + r*HN + 4);
        a[r][0]=v0.x; a[r][1]=v0.y; a[r][2]=v0.z; a[r][3]=v0.w;
        a[r][4]=v1.x; a[r][5]=v1.y; a[r][6]=v1.z; a[r][7]=v1.w;
    }
    haar_fwd<8>(a);
#pragma unroll
    for (int r = 0; r < 8; r++)
#pragma unroll
        for (int c = 0; c < 8; c++)
            if (r >= 4 || c >= 4) a[r][c] = softt(a[r][c]);
    haar_fwd<4>(a);
#pragma unroll
    for (int r = 0; r < 4; r++)
#pragma unroll
        for (int c = 0; c < 4; c++)
            if (r >= 2 || c >= 2) a[r][c] = softt(a[r][c]);
    haar_fwd<2>(a);
    a[0][1] = softt(a[0][1]);
    a[1][0] = softt(a[1][0]);
    a[1][1] = softt(a[1][1]);
    haar_inv<2>(a);
    haar_inv<4>(a);
    haar_inv<8>(a);
#pragma unroll
    for (int r = 0; r < 8; r++) {
        float4 xo0 = *(const float4*)(xold + base + r*HN);
        float4 xo1 = *(const float4*)(xold + base + r*HN + 4);
        float xov[8] = {xo0.x,xo0.y,xo0.z,xo0.w,xo1.x,xo1.y,xo1.z,xo1.w};
        float xn[8], zn[8];
#pragma unroll
        for (int c = 0; c < 8; c++) {
            float v = a[r][c];
            xn[c] = v;
            zn[c] = v + coef*(v - xov[c]);
        }
        *(float4*)(xnew + base + r*HN)     = make_float4(xn[0],xn[1],xn[2],xn[3]);
        *(float4*)(xnew + base + r*HN + 4) = make_float4(xn[4],xn[5],xn[6],xn[7]);
        *(float4*)(znew + base + r*HN)     = make_float4(zn[0],zn[1],zn[2],zn[3]);
        *(float4*)(znew + base + r*HN + 4) = make_float4(zn[4],zn[5],zn[6],zn[7]);
    }
}

// ---------------- host ----------------
extern "C" void kernel_launch(void* const* d_in, const int* in_sizes, int n_in,
                              void* d_out, int out_size) {
    (void)in_sizes; (void)n_in; (void)out_size;
    const float* y = (const float*)d_in[0];
    const float* mask = (const float*)d_in[1];
    float* out = (float*)d_out;

    float *Z, *X, *T1, *T2;
    float2 *T1c, *T2c;
    cudaGetSymbolAddress((void**)&Z,   g_Z);
    cudaGetSymbolAddress((void**)&X,   g_X);
    cudaGetSymbolAddress((void**)&T1,  g_T1);
    cudaGetSymbolAddress((void**)&T2,  g_T2);
    cudaGetSymbolAddress((void**)&T1c, g_T1c);
    cudaGetSymbolAddress((void**)&T2c, g_T2c);

    float coefs[15];
    {
        double t = 1.0;
        for (int k = 0; k < 15; k++) {
            double tn = (1.0 + sqrt(1.0 + 4.0*t*t)) / 2.0;
            coefs[k] = (float)((t - 1.0) / tn);
            t = tn;
        }
    }

    k_tw<<<1, 320>>>();
    k_prep<<<1600, 256>>>(y, mask);
    // x0 = ifft2c(y)
    k_fft_p2c<<<FGRID, FTH>>>(y, T1c, -1.f, 1.0f);
    k_fft_c2p<<<FGRID, FTH>>>(T1c, X, Z, -1.f, 1.f/320.f);

    for (int it = 0; it < 15; it++) {
        k_fft_p2c<<<FGRID, FTH>>>(Z, T1c, 1.f, 1.f/320.f);
        k_fft_mid<<<FGRID, FTH>>>(T1c, T2c);
        k_fft_last<<<FGRID, FTH>>>(T2c, Z, T1);       // T1 = z_step
        k_tv<<<3200, TVTH>>>(T1, T2);                 // T2 = x_tv
        float* xnew = (it == 14) ? out : X;
        k_wav<<<200, 256>>>(T2, X, xnew, Z, coefs[it]);
    }
}

// round 5
// speedup vs baseline: 1.1388x; 1.1027x over previous
#include <cuda_runtime.h>
#include <math.h>

#define HN 320
#define NPLANE (HN*HN)
#define NB 16
#define NTOT (NB*2*NPLANE)
#define LPC 4
#define FTH 128
#define GRPS (HN/LPC)
#define FGRID (NB*GRPS)          // 1280
#define LAM_TV 0.005f
#define LAM_W  0.005f
#define INV_S2 0.70710678118654752f

__device__ float  g_Z[NTOT];
__device__ float  g_X[NTOT];
__device__ float  g_T1[NTOT];            // planar z_step
__device__ float  g_T2[NTOT];            // planar x_tv
__device__ float2 g_T1c[NB*NPLANE];      // complex temp
__device__ float2 g_T2c[NB*NPLANE];      // complex temp
__device__ float2 g_ykc[NB*NPLANE];      // D*mask*y, transposed
__device__ float  g_mT[NB*NPLANE];       // mask, transposed
__device__ float2 g_tw[HN];

// ---------------- twiddles ----------------
__global__ void k_tw() {
    int k = threadIdx.x;
    if (k < HN) {
        double a = -2.0 * 3.14159265358979323846 * (double)k / (double)HN;
        g_tw[k] = make_float2((float)cos(a), (float)sin(a));
    }
}

// ---------------- prep ----------------
__global__ void __launch_bounds__(256) k_prep(const float* __restrict__ y,
                                              const float* __restrict__ mask) {
    __shared__ float sm[32][33], s0[32][33], s1[32][33];
    int b = blockIdx.x / 100, t = blockIdx.x % 100;
    int h0 = (t / 10) * 32, w0 = (t % 10) * 32;
    for (int i = threadIdx.x; i < 1024; i += 256) {
        int r = i >> 5, c = i & 31;
        sm[r][c] = mask[b*NPLANE + (h0+r)*HN + w0+c];
        s0[r][c] = y[(b*2+0)*NPLANE + (h0+r)*HN + w0+c];
        s1[r][c] = y[(b*2+1)*NPLANE + (h0+r)*HN + w0+c];
    }
    __syncthreads();
    for (int i = threadIdx.x; i < 1024; i += 256) {
        int ww = i >> 5, hh = i & 31;
        float sg = (((h0+hh) + (w0+ww)) & 1) ? -1.f : 1.f;
        float m = sm[hh][ww];
        int o = (w0+ww)*HN + h0+hh;
        g_mT[b*NPLANE + o] = m;
        g_ykc[b*NPLANE + o] = make_float2(sg*m*s0[hh][ww], sg*m*s1[hh][ww]);
    }
}

// ---------------- register/shuffle 320-pt FFT:  320 = 32(lanes) x 10(slots) ----------------
__device__ __forceinline__ float2 cmul(float2 a, float2 b) {
    return make_float2(a.x*b.x - a.y*b.y, a.x*b.y + a.y*b.x);
}

__device__ __forceinline__ void dft5(float2* v, float d) {
    const float c1 = 0.30901699437494742f, c2 = -0.80901699437494745f;
    const float s1 = 0.95105651629515353f, s2 = 0.58778525229247312f;
    float t1r=v[1].x+v[4].x, t1i=v[1].y+v[4].y;
    float t2r=v[2].x+v[3].x, t2i=v[2].y+v[3].y;
    float t3r=v[1].x-v[4].x, t3i=v[1].y-v[4].y;
    float t4r=v[2].x-v[3].x, t4i=v[2].y-v[3].y;
    float v0r=v[0].x, v0i=v[0].y;
    v[0] = make_float2(v0r+t1r+t2r, v0i+t1i+t2i);
    float a1r=v0r+c1*t1r+c2*t2r, a1i=v0i+c1*t1i+c2*t2i;
    float b1r=s1*t3r+s2*t4r,     b1i=s1*t3i+s2*t4i;
    float a2r=v0r+c2*t1r+c1*t2r, a2i=v0i+c2*t1i+c1*t2i;
    float b2r=s2*t3r-s1*t4r,     b2i=s2*t3i-s1*t4i;
    v[1] = make_float2(a1r + d*b1i, a1i - d*b1r);
    v[2] = make_float2(a2r + d*b2i, a2i - d*b2r);
    v[3] = make_float2(a2r - d*b2i, a2i + d*b2r);
    v[4] = make_float2(a1r - d*b1i, a1i + d*b1r);
}

// 10-pt DFT in place: out[k] = sum_n in[n] * exp(-2*pi*i*d*n*k/10)
__device__ __forceinline__ void dft10(float2* x, float d) {
    float2 E[5], O[5];
#pragma unroll
    for (int j = 0; j < 5; j++) { E[j] = x[2*j]; O[j] = x[2*j+1]; }
    dft5(E, d); dft5(O, d);
    const float C10[5] = {1.f, 0.80901699437494745f, 0.30901699437494742f,
                          -0.30901699437494742f, -0.80901699437494745f};
    const float S10[5] = {0.f, 0.58778525229247312f, 0.95105651629515353f,
                          0.95105651629515353f, 0.58778525229247312f};
#pragma unroll
    for (int k = 0; k < 5; k++) {
        float2 w = make_float2(C10[k], -d*S10[k]);
        float2 t = cmul(w, O[k]);
        x[k]   = make_float2(E[k].x + t.x, E[k].y + t.y);
        x[k+5] = make_float2(E[k].x - t.x, E[k].y - t.y);
    }
}

// cross-lane 32-pt DFT, DIF: natural lane order in, bit-reversed lane order out.
__device__ __forceinline__ void xfft32_dif(float2* x, const float2* stw, int lane, float d) {
#pragma unroll
    for (int s = 0; s < 5; s++) {
        const int m = 16 >> s;
        bool bot = (lane & m) != 0;
        int e = (lane & (m-1)) * ((16/m) * 10);
        float2 t = stw[e];
        float2 w = bot ? make_float2(t.x, d*t.y) : make_float2(1.f, 0.f);
        float sg = bot ? -1.f : 1.f;
#pragma unroll
        for (int j = 0; j < 10; j++) {
            float orr = __shfl_xor_sync(0xffffffffu, x[j].x, m);
            float oii = __shfl_xor_sync(0xffffffffu, x[j].y, m);
            float tr = orr + sg*x[j].x;
            float ti = oii + sg*x[j].y;
            x[j] = make_float2(tr*w.x - ti*w.y, tr*w.y + ti*w.x);
        }
    }
}

// cross-lane 32-pt INVERSE DFT, DIT: bit-reversed lane order in, natural out.
__device__ __forceinline__ void xfft32_dit_inv(float2* x, const float2* stw, int lane) {
#pragma unroll
    for (int s = 0; s < 5; s++) {
        const int m = 1 << s;
        bool bot = (lane & m) != 0;
        int e = (lane & (m-1)) * ((16/m) * 10);
        float2 t = stw[e];
        float2 w = make_float2(t.x, -t.y);
        float sg = bot ? -1.f : 1.f;
#pragma unroll
        for (int j = 0; j < 10; j++) {
            float orr = __shfl_xor_sync(0xffffffffu, x[j].x, m);
            float oii = __shfl_xor_sync(0xffffffffu, x[j].y, m);
            float pr = bot ? x[j].x : orr,  pi = bot ? x[j].y : oii;
            float qr = bot ? orr : x[j].x,  qi = bot ? oii : x[j].y;
            float wpr = pr*w.x - pi*w.y;
            float wpi = pr*w.y + pi*w.x;
            x[j] = make_float2(qr + sg*wpr, qi + sg*wpi);
        }
    }
}

// forward chain: natural x[10*lane+j] -> X[32*j + brev(lane)] in slot j
__device__ __forceinline__ int fwd320(float2* x, const float2* stw, int lane, float d) {
    xfft32_dif(x, stw, lane, d);
    int k1 = __brev(lane) >> 27;
#pragma unroll
    for (int j = 1; j < 10; j++) {
        float2 t = stw[j*k1];
        x[j] = cmul(x[j], make_float2(t.x, d*t.y));
    }
    dft10(x, d);
    return k1;
}

// inverse chain from spectral layout: X[32*j + brev(lane)] -> x[10*lane+j] (natural)
__device__ __forceinline__ void inv320(float2* x, const float2* stw, int lane) {
    int k1 = __brev(lane) >> 27;
    dft10(x, -1.f);
#pragma unroll
    for (int j = 1; j < 10; j++) {
        float2 t = stw[j*k1];
        x[j] = cmul(x[j], make_float2(t.x, -t.y));
    }
    xfft32_dit_inv(x, stw, lane);
}

// ---------------- planar -> complex transposed (sign+scale at load) ----------------
__global__ void __launch_bounds__(FTH) k_fft_p2c(const float* __restrict__ src,
                                                 float2* __restrict__ dst,
                                                 float d, float scale) {
    __shared__ float2 stw[HN];
    __shared__ float2 SL[LPC][HN];
    int img = blockIdx.x / GRPS, r0 = (blockIdx.x % GRPS) * LPC;
    for (int i = threadIdx.x; i < HN; i += FTH) stw[i] = g_tw[i];
    __syncthreads();
    int warp = threadIdx.x >> 5, lane = threadIdx.x & 31;
    int r = r0 + warp;
    float2 x[10];
    float sgE = ((r) & 1) ? -scale : scale;
    float sgO = -sgE;
    const float2* sre = (const float2*)(src + (img*2+0)*NPLANE + r*HN + 10*lane);
    const float2* sim = (const float2*)(src + (img*2+1)*NPLANE + r*HN + 10*lane);
#pragma unroll
    for (int j = 0; j < 5; j++) {
        float2 vr = sre[j], vi = sim[j];
        x[2*j]   = make_float2(sgE*vr.x, sgE*vi.x);
        x[2*j+1] = make_float2(sgO*vr.y, sgO*vi.y);
    }
    int k1 = fwd320(x, stw, lane, d);
#pragma unroll
    for (int j = 0; j < 10; j++) SL[warp][32*j + k1] = x[j];
    __syncthreads();
    float2* D = dst + img*NPLANE;
    for (int i = threadIdx.x; i < LPC*HN; i += FTH) {
        int s = i & (LPC-1), k = i >> 2;
        D[k*HN + r0 + s] = SL[s][k];
    }
}

// ---------------- complex -> planar transposed, dual dst (init pass 2) ----------------
__global__ void __launch_bounds__(FTH) k_fft_c2p(const float2* __restrict__ src,
                                                 float* __restrict__ dstA,
                                                 float* __restrict__ dstB,
                                                 float d, float scale) {
    __shared__ float2 stw[HN];
    __shared__ float2 SL[LPC][HN];
    int img = blockIdx.x / GRPS, r0 = (blockIdx.x % GRPS) * LPC;
    for (int i = threadIdx.x; i < HN; i += FTH) stw[i] = g_tw[i];
    __syncthreads();
    int warp = threadIdx.x >> 5, lane = threadIdx.x & 31;
    int r = r0 + warp;
    float2 x[10];
    const float4* S4 = (const float4*)(src + img*NPLANE + r*HN + 10*lane);
#pragma unroll
    for (int j = 0; j < 5; j++) {
        float4 v = S4[j];
        x[2*j]   = make_float2(v.x, v.y);
        x[2*j+1] = make_float2(v.z, v.w);
    }
    int k1 = fwd320(x, stw, lane, d);
#pragma unroll
    for (int j = 0; j < 10; j++) SL[warp][32*j + k1] = x[j];
    __syncthreads();
    for (int i = threadIdx.x; i < LPC*HN; i += FTH) {
        int s = i & (LPC-1), k = i >> 2;
        float sg = ((k + r0 + s) & 1) ? -scale : scale;
        float2 v = SL[s][k];
        int o = k*HN + r0 + s;
        dstA[(img*2+0)*NPLANE + o] = sg*v.x;
        dstA[(img*2+1)*NPLANE + o] = sg*v.y;
        dstB[(img*2+0)*NPLANE + o] = sg*v.x;
        dstB[(img*2+1)*NPLANE + o] = sg*v.y;
    }
}

// ---------------- fwd col-FFT + mask + inv col-FFT (no reorder between!) ----------------
__global__ void __launch_bounds__(FTH) k_fft_mid(const float2* __restrict__ src,
                                                 float2* __restrict__ dst) {
    __shared__ float2 stw[HN];
    __shared__ float2 SL[LPC][HN];
    int img = blockIdx.x / GRPS, r0 = (blockIdx.x % GRPS) * LPC;
    for (int i = threadIdx.x; i < HN; i += FTH) stw[i] = g_tw[i];
    __syncthreads();
    int warp = threadIdx.x >> 5, lane = threadIdx.x & 31;
    int r = r0 + warp;
    float2 x[10];
    const float4* S4 = (const float4*)(src + img*NPLANE + r*HN + 10*lane);
#pragma unroll
    for (int j = 0; j < 5; j++) {
        float4 v = S4[j];
        x[2*j]   = make_float2(v.x, v.y);
        x[2*j+1] = make_float2(v.z, v.w);
    }
    int k1 = fwd320(x, stw, lane, 1.f);
    // pointwise: spectrum index kk = 32*j + k1 (within-128B permutation -> coalesced)
    const float*  mrow = g_mT  + img*NPLANE + r*HN;
    const float2* ykr  = g_ykc + img*NPLANE + r*HN;
#pragma unroll
    for (int j = 0; j < 10; j++) {
        int kk = 32*j + k1;
        float m = mrow[kk];
        float2 yk = ykr[kk];
        x[j] = make_float2(x[j].x*m - yk.x, x[j].y*m - yk.y);
    }
    inv320(x, stw, lane);
#pragma unroll
    for (int j = 0; j < 10; j++) SL[warp][10*lane + j] = x[j];
    __syncthreads();
    float2* D = dst + img*NPLANE;
    for (int i = threadIdx.x; i < LPC*HN; i += FTH) {
        int s = i & (LPC-1), k = i >> 2;
        D[k*HN + r0 + s] = SL[s][k];
    }
}

// ---------------- inv row-FFT + fused z_step = z - g ----------------
__global__ void __launch_bounds__(FTH) k_fft_last(const float2* __restrict__ src,
                                                  const float* __restrict__ zin,
                                                  float* __restrict__ zs) {
    __shared__ float2 stw[HN];
    __shared__ float2 SL[LPC][HN];
    int img = blockIdx.x / GRPS, r0 = (blockIdx.x % GRPS) * LPC;
    for (int i = threadIdx.x; i < HN; i += FTH) stw[i] = g_tw[i];
    __syncthreads();
    int warp = threadIdx.x >> 5, lane = threadIdx.x & 31;
    int r = r0 + warp;
    float2 x[10];
    const float4* S4 = (const float4*)(src + img*NPLANE + r*HN + 10*lane);
#pragma unroll
    for (int j = 0; j < 5; j++) {
        float4 v = S4[j];
        x[2*j]   = make_float2(v.x, v.y);
        x[2*j+1] = make_float2(v.z, v.w);
    }
    int k1 = fwd320(x, stw, lane, -1.f);   // inverse via conjugated forward network
#pragma unroll
    for (int j = 0; j < 10; j++) SL[warp][32*j + k1] = x[j];
    __syncthreads();
    const float sc = 1.f/320.f;
    for (int i = threadIdx.x; i < LPC*HN; i += FTH) {
        int s = i / HN, w = i - s*HN;
        float sg = (((r0+s) + w) & 1) ? -sc : sc;
        float2 v = SL[s][w];
        int oR = (img*2+0)*NPLANE + (r0+s)*HN + w;
        int oI = (img*2+1)*NPLANE + (r0+s)*HN + w;
        zs[oR] = zin[oR] - sg*v.x;
        zs[oI] = zin[oI] - sg*v.y;
    }
}

// ---------------- TV prox: 5 fused Chambolle iterations per tile ----------------
#define TS 32
#define HL 6
#define TP 44
#define TPS 45
#define TVTH 512
__global__ void __launch_bounds__(TVTH) k_tv(const float* __restrict__ xin,
                                             float* __restrict__ xout) {
    __shared__ float sx[TP*TPS], su[TP*TPS], spx[TP*TPS], spy[TP*TPS];
    int plane = blockIdx.x / 100;
    int t = blockIdx.x % 100;
    int gy0 = (t / 10) * TS - HL;
    int gx0 = (t % 10) * TS - HL;
    const float* X = xin + plane*NPLANE;
    for (int i = threadIdx.x; i < TP*TP; i += TVTH) {
        int r = i / TP, c = i - r*TP;
        int gy = gy0 + r, gx = gx0 + c;
        float v = 0.f;
        if (gy >= 0 && gy < HN && gx >= 0 && gx < HN) v = X[gy*HN + gx];
        sx[r*TPS+c] = v;
        spx[r*TPS+c] = 0.f;
        spy[r*TPS+c] = 0.f;
    }
    __syncthreads();
    for (int it = 0; it < 5; it++) {
        for (int i = threadIdx.x; i < TP*TP; i += TVTH) {
            int r = i / TP, c = i - r*TP;
            int gy = gy0 + r, gx = gx0 + c;
            float px_c = spx[r*TPS+c];
            float px_l = (c > 0) ? spx[r*TPS+c-1] : 0.f;
            float dx = (gx == 0) ? px_c : ((gx == HN-1) ? -px_l : px_c - px_l);
            float py_c = spy[r*TPS+c];
            float py_u = (r > 0) ? spy[(r-1)*TPS+c] : 0.f;
            float dy = (gy == 0) ? py_c : ((gy == HN-1) ? -py_u : py_c - py_u);
            su[r*TPS+c] = sx[r*TPS+c] - LAM_TV * (dx + dy);
        }
        __syncthreads();
        for (int i = threadIdx.x; i < TP*TP; i += TVTH) {
            int r = i / TP, c = i - r*TP;
            int gy = gy0 + r, gx = gx0 + c;
            float uc = su[r*TPS+c];
            float gxv = 0.f, gyv = 0.f;
            if (gx < HN-1 && c < TP-1) gxv = su[r*TPS+c+1] - uc;
            if (gy < HN-1 && r < TP-1) gyv = su[(r+1)*TPS+c] - uc;
            float pnx = spx[r*TPS+c] + 0.25f*gxv;
            float pny = spy[r*TPS+c] + 0.25f*gyv;
            float nrm = sqrtf(pnx*pnx + pny*pny + 1e-8f);
            float inv = (nrm > 1.f) ? 1.f/nrm : 1.f;
            if (gy < 0 || gy >= HN || gx < 0 || gx >= HN) { pnx = 0.f; pny = 0.f; inv = 1.f; }
            spx[r*TPS+c] = pnx*inv;
            spy[r*TPS+c] = pny*inv;
        }
        __syncthreads();
    }
    float* O = xout + plane*NPLANE;
    for (int i = threadIdx.x; i < TS*TS; i += TVTH) {
        int r = i / TS + HL, c = i - (r-HL)*TS + HL;
        int gy = gy0 + r, gx = gx0 + c;
        float px_c = spx[r*TPS+c];
        float px_l = spx[r*TPS+c-1];
        float dx = (gx == 0) ? px_c : ((gx == HN-1) ? -px_l : px_c - px_l);
        float py_c = spy[r*TPS+c];
        float py_u = spy[(r-1)*TPS+c];
        float dy = (gy == 0) ? py_c : ((gy == HN-1) ? -py_u : py_c - py_u);
        O[gy*HN + gx] = sx[r*TPS+c] - LAM_TV * (dx + dy);
    }
}

// ---------------- 3-level Haar + soft-threshold + FISTA, 8x8 per thread ----------------
template<int n>
__device__ __forceinline__ void haar_fwd(float a[8][8]) {
#pragma unroll
    for (int r = 0; r < n; r++) {
        float t[8];
#pragma unroll
        for (int j = 0; j < n/2; j++) {
            t[j]     = (a[r][2*j] + a[r][2*j+1]) * INV_S2;
            t[j+n/2] = (a[r][2*j] - a[r][2*j+1]) * INV_S2;
        }
#pragma unroll
        for (int j = 0; j < n; j++) a[r][j] = t[j];
    }
#pragma unroll
    for (int c = 0; c < n; c++) {
        float t[8];
#pragma unroll
        for (int j = 0; j < n/2; j++) {
            t[j]     = (a[2*j][c] + a[2*j+1][c]) * INV_S2;
            t[j+n/2] = (a[2*j][c] - a[2*j+1][c]) * INV_S2;
        }
#pragma unroll
        for (int j = 0; j < n; j++) a[j][c] = t[j];
    }
}

template<int n>
__device__ __forceinline__ void haar_inv(float a[8][8]) {
#pragma unroll
    for (int c = 0; c < n; c++) {
        float t[8];
#pragma unroll
        for (int j = 0; j < n/2; j++) {
            t[2*j]   = (a[j][c] + a[j+n/2][c]) * INV_S2;
            t[2*j+1] = (a[j][c] - a[j+n/2][c]) * INV_S2;
        }
#pragma unroll
        for (int j = 0; j < n; j++) a[j][c] = t[j];
    }
#pragma unroll
    for (int r = 0; r < n; r++) {
        float t[8];
#pragma unroll
        for (int j = 0; j < n/2; j++) {
            t[2*j]   = (a[r][j] + a[r][j+n/2]) * INV_S2;
            t[2*j+1] = (a[r][j] - a[r][j+n/2]) * INV_S2;
        }
#pragma unroll
        for (int j = 0; j < n; j++) a[r][j] = t[j];
    }
}

__device__ __forceinline__ float softt(float v) {
    float m = fabsf(v) - LAM_W;
    return (m > 0.f) ? copysignf(m, v) : 0.f;
}

__global__ void __launch_bounds__(256) k_wav(const float* __restrict__ xtv,
                                             const float* __restrict__ xold,
                                             float* __restrict__ xnew,
                                             float* __restrict__ znew,
                                             float coef) {
    int tid = blockIdx.x * 256 + threadIdx.x;
    if (tid >= 32*1600) return;
    int plane = tid / 1600, blk = tid - plane*1600;
    int by = (blk / 40) * 8, bx = (blk % 40) * 8;
    int base = plane*NPLANE + by*HN + bx;
    float a[8][8];
#pragma unroll
    for (int r = 0; r < 8; r++) {
        float4 v0 = *(const float4*)(xtv + base + r*HN);
        float4 v1 = *(const float4*)(xtv + base + r*HN + 4);
        a[r][0]=v0.x; a[r][1]=v0.y; a[r][2]=v0.z; a[r][3]=v0.w;
        a[r][4]=v1.x; a[r][5]=v1.y; a[r][6]=v1.z; a[r][7]=v1.w;
    }
    haar_fwd<8>(a);
#pragma unroll
    for (int r = 0; r < 8; r++)
#pragma unroll
        for (int c = 0; c < 8; c++)
            if (r >= 4 || c >= 4) a[r][c] = softt(a[r][c]);
    haar_fwd<4>(a);
#pragma unroll
    for (int r = 0; r < 4; r++)
#pragma unroll
        for (int c = 0; c < 4; c++)
            if (r >= 2 || c >= 2) a[r][c] = softt(a[r][c]);
    haar_fwd<2>(a);
    a[0][1] = softt(a[0][1]);
    a[1][0] = softt(a[1][0]);
    a[1][1] = softt(a[1][1]);
    haar_inv<2>(a);
    haar_inv<4>(a);
    haar_inv<8>(a);
#pragma unroll
    for (int r = 0; r < 8; r++) {
        float4 xo0 = *(const float4*)(xold + base + r*HN);
        float4 xo1 = *(const float4*)(xold + base + r*HN + 4);
        float xov[8] = {xo0.x,xo0.y,xo0.z,xo0.w,xo1.x,xo1.y,xo1.z,xo1.w};
        float xn[8], zn[8];
#pragma unroll
        for (int c = 0; c < 8; c++) {
            float v = a[r][c];
            xn[c] = v;
            zn[c] = v + coef*(v - xov[c]);
        }
        *(float4*)(xnew + base + r*HN)     = make_float4(xn[0],xn[1],xn[2],xn[3]);
        *(float4*)(xnew + base + r*HN + 4) = make_float4(xn[4],xn[5],xn[6],xn[7]);
        *(float4*)(znew + base + r*HN)     = make_float4(zn[0],zn[1],zn[2],zn[3]);
        *(float4*)(znew + base + r*HN + 4) = make_float4(zn[4],zn[5],zn[6],zn[7]);
    }
}

// ---------------- host ----------------
extern "C" void kernel_launch(void* const* d_in, const int* in_sizes, int n_in,
                              void* d_out, int out_size) {
    (void)in_sizes; (void)n_in; (void)out_size;
    const float* y = (const float*)d_in[0];
    const float* mask = (const float*)d_in[1];
    float* out = (float*)d_out;

    float *Z, *X, *T1, *T2;
    float2 *T1c, *T2c;
    cudaGetSymbolAddress((void**)&Z,   g_Z);
    cudaGetSymbolAddress((void**)&X,   g_X);
    cudaGetSymbolAddress((void**)&T1,  g_T1);
    cudaGetSymbolAddress((void**)&T2,  g_T2);
    cudaGetSymbolAddress((void**)&T1c, g_T1c);
    cudaGetSymbolAddress((void**)&T2c, g_T2c);

    float coefs[15];
    {
        double t = 1.0;
        for (int k = 0; k < 15; k++) {
            double tn = (1.0 + sqrt(1.0 + 4.0*t*t)) / 2.0;
            coefs[k] = (float)((t - 1.0) / tn);
            t = tn;
        }
    }

    k_tw<<<1, 320>>>();
    k_prep<<<1600, 256>>>(y, mask);
    k_fft_p2c<<<FGRID, FTH>>>(y, T1c, -1.f, 1.0f);
    k_fft_c2p<<<FGRID, FTH>>>(T1c, X, Z, -1.f, 1.f/320.f);

    for (int it = 0; it < 15; it++) {
        k_fft_p2c<<<FGRID, FTH>>>(Z, T1c, 1.f, 1.f/320.f);
        k_fft_mid<<<FGRID, FTH>>>(T1c, T2c);
        k_fft_last<<<FGRID, FTH>>>(T2c, Z, T1);       // T1 = z_step
        k_tv<<<3200, TVTH>>>(T1, T2);                 // T2 = x_tv
        float* xnew = (it == 14) ? out : X;
        k_wav<<<200, 256>>>(T2, X, xnew, Z, coefs[it]);
    }
}